// round 16
// baseline (speedup 1.0000x reference)
#include <cuda_runtime.h>
#include <cuda_fp16.h>
#include <math.h>

#define DHH 128
#define NMAX 50000
#define EMAX 800000
#define MT 64            // nodes per C tile
#define NTILES 16        // 16 n-tiles of 8 = 128 output feats
#define KST 16           // K-steps of 16 over fused K=256
#define THREADS_G 1024   // GEMM block: 32 warps
#define A_STRIDE 132                               // 128 k-pairs + 4 pad
#define SMEM_W_BYTES (KST * NTILES * 32 * 16)      // 8192 uint4 = 131072
#define SMEM_A_UINTS (MT * A_STRIDE)               // 8448
#define SMEM_TOTAL_BYTES (SMEM_W_BYTES + 2 * SMEM_A_UINTS * 4)

// Scratch (allocation-free: static device globals).
// ALL node features (x/h1/h2 AND the aggregated mean s) stored fp16-packed:
// 64 uints (fp16x2) per node.
__device__ __align__(16) unsigned g_sh [NMAX * 64];
__device__ __align__(16) unsigned g_xh [NMAX * 64];
__device__ __align__(16) unsigned g_h1h[NMAX * 64];
__device__ __align__(16) unsigned g_h2h[NMAX * 64];
__device__ __align__(16) uint4 g_wfrag[2 * 8192];  // pre-split W fragments
__device__ int g_deg[NMAX];
__device__ int g_start[NMAX];
__device__ int g_cursor[NMAX];
__device__ int g_esrc[EMAX];
__device__ int g_alloc_ctr;

// ---------------------------------------------------------------------------
// fp16 / bf16 helpers
// ---------------------------------------------------------------------------
__device__ __forceinline__ __half2 ash2(unsigned u) {
    return *reinterpret_cast<__half2*>(&u);
}
__device__ __forceinline__ unsigned packh2(float a, float b) {
    __half2 h = __floats2half2_rn(a, b);
    return *reinterpret_cast<unsigned*>(&h);
}
__device__ __forceinline__ float2 unpackh2(unsigned u) {
    return __half22float2(ash2(u));
}

__device__ __forceinline__ unsigned pack_bf16x2(float lo, float hi) {
    unsigned u;
    asm("cvt.rn.bf16x2.f32 %0, %1, %2;" : "=r"(u) : "f"(hi), "f"(lo));
    return u;
}

__device__ __forceinline__ void split2(float x, float y, unsigned& hi, unsigned& lo) {
    hi = pack_bf16x2(x, y);
    float xh = __uint_as_float(hi << 16);
    float yh = __uint_as_float(hi & 0xffff0000u);
    lo = pack_bf16x2(x - xh, y - yh);
}

__device__ __forceinline__ void mma16(float* c, const unsigned* a, unsigned b0, unsigned b1) {
    asm volatile("mma.sync.aligned.m16n8k16.row.col.f32.bf16.bf16.f32 "
        "{%0,%1,%2,%3}, {%4,%5,%6,%7}, {%8,%9}, {%0,%1,%2,%3};"
        : "+f"(c[0]), "+f"(c[1]), "+f"(c[2]), "+f"(c[3])
        : "r"(a[0]), "r"(a[1]), "r"(a[2]), "r"(a[3]), "r"(b0), "r"(b1));
}

// ---------------------------------------------------------------------------
// Convert x (f32) -> fp16
// ---------------------------------------------------------------------------
__global__ void convert_x(const float2* __restrict__ x, unsigned* __restrict__ xh, int n) {
    int i = blockIdx.x * blockDim.x + threadIdx.x;
    if (i < n) {
        float2 v = __ldg(&x[i]);
        xh[i] = packh2(v.x, v.y);
    }
}

// ---------------------------------------------------------------------------
// Prep: split W into bf16 hi/lo fragment order (see layout comment R4).
// ---------------------------------------------------------------------------
__global__ void prep_w(const float* __restrict__ W1l, const float* __restrict__ W1r,
                       const float* __restrict__ Whl, const float* __restrict__ Whr) {
    int idx = blockIdx.x * blockDim.x + threadIdx.x;
    if (idx >= 16384) return;
    int layer = idx >> 13;
    int rem = idx & 8191;
    int S = rem >> 9;
    int T = (rem >> 5) & 15;
    int lane = rem & 31;
    const float* W = (S < 8) ? (layer ? Whl : W1l) : (layer ? Whr : W1r);
    int k0 = (S & 7) * 16;
    int row = T * 8 + (lane >> 2);
    int cc = lane & 3;
    const float* p = W + row * DHH + k0 + 2 * cc;
    unsigned h0, l0, h1, l1;
    split2(__ldg(&p[0]), __ldg(&p[1]), h0, l0);
    split2(__ldg(&p[8]), __ldg(&p[9]), h1, l1);
    g_wfrag[idx] = make_uint4(h0, h1, l0, l1);
}

// ---------------------------------------------------------------------------
// CSR build: histogram -> warp-aggregated range allocation -> fill.
// (scalar forms: measured faster than 4-edge int4 variants in R15)
// ---------------------------------------------------------------------------
__global__ void hist_k(const int* __restrict__ ei, int E, int* __restrict__ deg) {
    int e = blockIdx.x * blockDim.x + threadIdx.x;
    if (e == 0) g_alloc_ctr = 0;   // nothing reads it until alloc_k
    if (e < E) atomicAdd(&deg[ei[E + e]], 1);
}

__global__ void alloc_k(const int* __restrict__ deg, int N,
                        int* __restrict__ start, int* __restrict__ cursor) {
    int i = blockIdx.x * blockDim.x + threadIdx.x;
    int lane = threadIdx.x & 31;
    int d = (i < N) ? deg[i] : 0;
    int pref = d;
    #pragma unroll
    for (int off = 1; off < 32; off <<= 1) {
        int v = __shfl_up_sync(0xffffffff, pref, off);
        if (lane >= off) pref += v;
    }
    int total = __shfl_sync(0xffffffff, pref, 31);
    int base = 0;
    if (lane == 31) base = atomicAdd(&g_alloc_ctr, total);
    base = __shfl_sync(0xffffffff, base, 31);
    int mybase = base + pref - d;
    if (i < N) {
        start[i] = mybase;
        cursor[i] = mybase;
    }
}

__global__ void fill_k(const int* __restrict__ ei, int E,
                       int* __restrict__ cursor, int* __restrict__ esrc) {
    int e = blockIdx.x * blockDim.x + threadIdx.x;
    if (e < E) {
        int dst = ei[E + e];
        int p = atomicAdd(&cursor[dst], 1);
        esrc[p] = ei[e];
    }
}

// ---------------------------------------------------------------------------
// Gather: one warp per dst node. fp16 feature reads, HADD2 partial sums over
// 4-edge groups, f32 master accumulator, fp16 packed output.
// Lane owns feats [4*lane .. 4*lane+3] = one uint2.
// ---------------------------------------------------------------------------
__global__ void gather_k(const uint2* __restrict__ feath, const int* __restrict__ start,
                         const int* __restrict__ deg, const int* __restrict__ esrc,
                         uint2* __restrict__ s, int N) {
    int n = blockIdx.x * 8 + (threadIdx.x >> 5);
    if (n >= N) return;
    int lane = threadIdx.x & 31;
    int beg = __ldg(&start[n]);
    int d = __ldg(&deg[n]);
    int end = beg + d;

    float4 acc = make_float4(0.f, 0.f, 0.f, 0.f);

    int e = beg;
    for (; e + 8 <= end; e += 8) {
        int s0 = __ldg(&esrc[e]),     s1 = __ldg(&esrc[e + 1]);
        int s2 = __ldg(&esrc[e + 2]), s3 = __ldg(&esrc[e + 3]);
        int s4 = __ldg(&esrc[e + 4]), s5 = __ldg(&esrc[e + 5]);
        int s6 = __ldg(&esrc[e + 6]), s7 = __ldg(&esrc[e + 7]);
        uint2 u0 = __ldg(&feath[(long long)s0 * 32 + lane]);
        uint2 u1 = __ldg(&feath[(long long)s1 * 32 + lane]);
        uint2 u2 = __ldg(&feath[(long long)s2 * 32 + lane]);
        uint2 u3 = __ldg(&feath[(long long)s3 * 32 + lane]);
        uint2 u4 = __ldg(&feath[(long long)s4 * 32 + lane]);
        uint2 u5 = __ldg(&feath[(long long)s5 * 32 + lane]);
        uint2 u6 = __ldg(&feath[(long long)s6 * 32 + lane]);
        uint2 u7 = __ldg(&feath[(long long)s7 * 32 + lane]);
        __half2 pa0 = __hadd2(ash2(u0.x), ash2(u1.x));
        __half2 pa1 = __hadd2(ash2(u0.y), ash2(u1.y));
        __half2 qa0 = __hadd2(ash2(u2.x), ash2(u3.x));
        __half2 qa1 = __hadd2(ash2(u2.y), ash2(u3.y));
        pa0 = __hadd2(pa0, qa0); pa1 = __hadd2(pa1, qa1);
        float2 fa0 = __half22float2(pa0), fa1 = __half22float2(pa1);
        acc.x += fa0.x; acc.y += fa0.y; acc.z += fa1.x; acc.w += fa1.y;
        __half2 pb0 = __hadd2(ash2(u4.x), ash2(u5.x));
        __half2 pb1 = __hadd2(ash2(u4.y), ash2(u5.y));
        __half2 qb0 = __hadd2(ash2(u6.x), ash2(u7.x));
        __half2 qb1 = __hadd2(ash2(u6.y), ash2(u7.y));
        pb0 = __hadd2(pb0, qb0); pb1 = __hadd2(pb1, qb1);
        float2 fb0 = __half22float2(pb0), fb1 = __half22float2(pb1);
        acc.x += fb0.x; acc.y += fb0.y; acc.z += fb1.x; acc.w += fb1.y;
    }
    for (; e + 4 <= end; e += 4) {
        int s0 = __ldg(&esrc[e]),     s1 = __ldg(&esrc[e + 1]);
        int s2 = __ldg(&esrc[e + 2]), s3 = __ldg(&esrc[e + 3]);
        uint2 u0 = __ldg(&feath[(long long)s0 * 32 + lane]);
        uint2 u1 = __ldg(&feath[(long long)s1 * 32 + lane]);
        uint2 u2 = __ldg(&feath[(long long)s2 * 32 + lane]);
        uint2 u3 = __ldg(&feath[(long long)s3 * 32 + lane]);
        __half2 p0 = __hadd2(ash2(u0.x), ash2(u1.x));
        __half2 p1 = __hadd2(ash2(u0.y), ash2(u1.y));
        __half2 q0 = __hadd2(ash2(u2.x), ash2(u3.x));
        __half2 q1 = __hadd2(ash2(u2.y), ash2(u3.y));
        p0 = __hadd2(p0, q0); p1 = __hadd2(p1, q1);
        float2 f0 = __half22float2(p0), f1 = __half22float2(p1);
        acc.x += f0.x; acc.y += f0.y; acc.z += f1.x; acc.w += f1.y;
    }
    for (; e < end; e++) {
        int s0 = __ldg(&esrc[e]);
        uint2 u0 = __ldg(&feath[(long long)s0 * 32 + lane]);
        float2 f0 = unpackh2(u0.x), f1 = unpackh2(u0.y);
        acc.x += f0.x; acc.y += f0.y; acc.z += f1.x; acc.w += f1.y;
    }

    float inv = 1.0f / fmaxf((float)d, 1.0f);
    uint2 r;
    r.x = packh2(acc.x * inv, acc.y * inv);
    r.y = packh2(acc.z * inv, acc.w * inv);
    s[(long long)n * 32 + lane] = r;
}

// ---------------------------------------------------------------------------
// Fused SAGE layer: C = act([agg | x] . [Wl|Wr]^T + bl), split-bf16 mma.
// Block: 1024 threads / 32 warps. Warp w: rowgroup g = w>>3 (16 rows),
// ntile pair q = w&7 (tiles 2q, 2q+1).
// Both inputs fp16-packed; output fp16-packed.
// ---------------------------------------------------------------------------
template <int ACT>
__global__ __launch_bounds__(THREADS_G, 1)
void sage_bf16(const uint2* __restrict__ xh, const uint2* __restrict__ sh,
               const uint4* __restrict__ wfrag, const float* __restrict__ bl,
               unsigned* __restrict__ outh, int N) {
    extern __shared__ char smemraw[];
    uint4*    shW  = (uint4*)smemraw;                       // [KST*NTILES*32] = 8192
    unsigned* shAh = (unsigned*)(smemraw + SMEM_W_BYTES);   // [MT][A_STRIDE]
    unsigned* shAl = shAh + SMEM_A_UINTS;

    int t = threadIdx.x;
    int w = t >> 5, lane = t & 31;
    int r = lane >> 2, c = lane & 3;
    int g = w >> 3;        // row-group 0..3
    int q = w & 7;         // ntile pair 0..7
    int mbase = g * 16;

    // 8192 uint4 entries staged by 1024 threads: 8 iterations.
    #pragma unroll
    for (int i = 0; i < 8; i++)
        shW[t + i * THREADS_G] = __ldg(&wfrag[t + i * THREADS_G]);

    float bias0[2], bias1[2];
    #pragma unroll
    for (int i = 0; i < 2; i++) {
        int colg = (q * 2 + i) * 8 + 2 * c;
        bias0[i] = __ldg(&bl[colg]);
        bias1[i] = __ldg(&bl[colg + 1]);
    }

    int mtiles = (N + MT - 1) / MT;
    for (int tile = blockIdx.x; tile < mtiles; tile += gridDim.x) {
        __syncthreads();
        int n0 = tile * MT;

        #pragma unroll
        for (int i = 0; i < 4; i++) {
            int flat = t + i * THREADS_G;
            int row = flat >> 6;
            int c4 = flat & 63;
            int node = n0 + row;
            float4 v = make_float4(0.f, 0.f, 0.f, 0.f);
            if (node < N) {
                uint2 u = (c4 < 32)
                    ? __ldg(&sh[(long long)node * 32 + c4])
                    : __ldg(&xh[(long long)node * 32 + (c4 - 32)]);
                float2 a = unpackh2(u.x), b = unpackh2(u.y);
                v = make_float4(a.x, a.y, b.x, b.y);
            }
            unsigned h01, l01, h23, l23;
            split2(v.x, v.y, h01, l01);
            split2(v.z, v.w, h23, l23);
            int base = row * A_STRIDE + c4 * 2;
            *(uint2*)&shAh[base] = make_uint2(h01, h23);
            *(uint2*)&shAl[base] = make_uint2(l01, l23);
        }
        __syncthreads();

        float acc[2][4];
        #pragma unroll
        for (int T = 0; T < 2; T++)
            acc[T][0] = acc[T][1] = acc[T][2] = acc[T][3] = 0.f;

        #pragma unroll 4
        for (int S = 0; S < KST; S++) {
            int ra = (mbase + r) * A_STRIDE + S * 8 + c;
            int rb = (mbase + r + 8) * A_STRIDE + S * 8 + c;
            unsigned ah[4], al[4];
            ah[0] = shAh[ra]; ah[1] = shAh[rb]; ah[2] = shAh[ra + 4]; ah[3] = shAh[rb + 4];
            al[0] = shAl[ra]; al[1] = shAl[rb]; al[2] = shAl[ra + 4]; al[3] = shAl[rb + 4];
            #pragma unroll
            for (int T = 0; T < 2; T++) {
                uint4 b = shW[(S * NTILES + q * 2 + T) * 32 + lane];
                mma16(acc[T], al, b.x, b.y);   // al*bh
                mma16(acc[T], ah, b.z, b.w);   // ah*bl
                mma16(acc[T], ah, b.x, b.y);   // ah*bh
            }
        }

        #pragma unroll
        for (int T = 0; T < 2; T++) {
            int colg = (q * 2 + T) * 8 + 2 * c;
            float v0 = acc[T][0] + bias0[T], v1 = acc[T][1] + bias1[T];
            float v2 = acc[T][2] + bias0[T], v3 = acc[T][3] + bias1[T];
            if (ACT == 0) {
                v0 = fmaxf(v0, 0.f); v1 = fmaxf(v1, 0.f);
                v2 = fmaxf(v2, 0.f); v3 = fmaxf(v3, 0.f);
            } else {
                v0 = (v0 > 0.f) ? v0 : expm1f(v0);
                v1 = (v1 > 0.f) ? v1 : expm1f(v1);
                v2 = (v2 > 0.f) ? v2 : expm1f(v2);
                v3 = (v3 > 0.f) ? v3 : expm1f(v3);
            }
            int node0 = n0 + mbase + r;
            int cw = colg >> 1;                 // uint word index within row
            if (node0 < N)
                outh[(long long)node0 * 64 + cw] = packh2(v0, v1);
            if (node0 + 8 < N)
                outh[(long long)(node0 + 8) * 64 + cw] = packh2(v2, v3);
        }
    }
}

// ---------------------------------------------------------------------------
// Output layer (DOUT=8) + log_softmax. One warp per node.
// Lane owns feats [4*lane..4*lane+3]; weights via vector LDG.128 (coalesced).
// ---------------------------------------------------------------------------
__global__ void sage_out_k(const uint2* __restrict__ xh, const uint2* __restrict__ sh,
                           const float* __restrict__ Wl, const float* __restrict__ bl,
                           const float* __restrict__ Wr,
                           float* __restrict__ out, int N) {
    long long tid = (long long)blockIdx.x * blockDim.x + threadIdx.x;
    int n = (int)(tid >> 5);
    if (n >= N) return;
    int lane = (int)(tid & 31);

    uint2 su = __ldg(&sh[(long long)n * 32 + lane]);
    uint2 xu = __ldg(&xh[(long long)n * 32 + lane]);
    float2 s01 = unpackh2(su.x), s23 = unpackh2(su.y);
    float2 x01 = unpackh2(xu.x), x23 = unpackh2(xu.y);

    float acc[8];
    #pragma unroll
    for (int j = 0; j < 8; j++) {
        float4 wl = __ldg((const float4*)(Wl + j * DHH) + lane);
        float4 wr = __ldg((const float4*)(Wr + j * DHH) + lane);
        acc[j] = s01.x * wl.x + s01.y * wl.y + s23.x * wl.z + s23.y * wl.w
               + x01.x * wr.x + x01.y * wr.y + x23.x * wr.z + x23.y * wr.w;
    }

    #pragma unroll
    for (int j = 0; j < 8; j++) {
        #pragma unroll
        for (int off = 16; off > 0; off >>= 1)
            acc[j] += __shfl_xor_sync(0xffffffff, acc[j], off);
    }

    if (lane == 0) {
        float h[8];
        float m = -1e30f;
        #pragma unroll
        for (int j = 0; j < 8; j++) {
            h[j] = acc[j] + bl[j];
            m = fmaxf(m, h[j]);
        }
        float sum = 0.0f;
        #pragma unroll
        for (int j = 0; j < 8; j++) sum += expf(h[j] - m);
        float lse = logf(sum) + m;
        #pragma unroll
        for (int j = 0; j < 8; j++) out[(long long)n * 8 + j] = h[j] - lse;
    }
}

// ---------------------------------------------------------------------------
extern "C" void kernel_launch(void* const* d_in, const int* in_sizes, int n_in,
                              void* d_out, int out_size) {
    const float* x   = (const float*)d_in[0];
    const int*   ei  = (const int*)d_in[1];
    // d_in[2] = edge_attr, unused
    const float* W1l = (const float*)d_in[3];
    const float* b1l = (const float*)d_in[4];
    const float* W1r = (const float*)d_in[5];
    const float* Whl = (const float*)d_in[6];
    const float* bhl = (const float*)d_in[7];
    const float* Whr = (const float*)d_in[8];
    const float* W2l = (const float*)d_in[9];
    const float* b2l = (const float*)d_in[10];
    const float* W2r = (const float*)d_in[11];
    float* out = (float*)d_out;

    int N = in_sizes[0] / DHH;
    int E = in_sizes[1] / 2;

    unsigned *sh, *xh, *h1h, *h2h;
    uint4* wfrag;
    int *deg, *start, *cursor, *esrc;
    cudaGetSymbolAddress((void**)&sh, g_sh);
    cudaGetSymbolAddress((void**)&xh, g_xh);
    cudaGetSymbolAddress((void**)&h1h, g_h1h);
    cudaGetSymbolAddress((void**)&h2h, g_h2h);
    cudaGetSymbolAddress((void**)&wfrag, g_wfrag);
    cudaGetSymbolAddress((void**)&deg, g_deg);
    cudaGetSymbolAddress((void**)&start, g_start);
    cudaGetSymbolAddress((void**)&cursor, g_cursor);
    cudaGetSymbolAddress((void**)&esrc, g_esrc);

    cudaFuncSetAttribute(sage_bf16<0>, cudaFuncAttributeMaxDynamicSharedMemorySize,
                         SMEM_TOTAL_BYTES);
    cudaFuncSetAttribute(sage_bf16<1>, cudaFuncAttributeMaxDynamicSharedMemorySize,
                         SMEM_TOTAL_BYTES);

    int egrid = (E + 255) / 256;
    int ngrid = (N + 255) / 256;
    int cgrid = (N * 64 + 255) / 256;
    int ggrid = 148;
    int agrid = (N + 7) / 8;
    int ogrid = (int)(((long long)N * 32 + 255) / 256);

    // CSR build + fp16 conversion of x
    cudaMemsetAsync(deg, 0, (size_t)N * sizeof(int), 0);
    convert_x<<<cgrid, 256>>>((const float2*)x, xh, N * 64);
    hist_k<<<egrid, 256>>>(ei, E, deg);
    alloc_k<<<ngrid, 256>>>(deg, N, start, cursor);
    fill_k<<<egrid, 256>>>(ei, E, cursor, esrc);

    // Layer 1 (prep_w needs to finish only before sage_bf16<0>)
    gather_k<<<agrid, 256>>>((const uint2*)xh, start, deg, esrc, (uint2*)sh, N);
    prep_w<<<64, 256>>>(W1l, W1r, Whl, Whr);
    sage_bf16<0><<<ggrid, THREADS_G, SMEM_TOTAL_BYTES>>>((const uint2*)xh, (const uint2*)sh,
                                                         wfrag, b1l, h1h, N);

    // Layer 2
    gather_k<<<agrid, 256>>>((const uint2*)h1h, start, deg, esrc, (uint2*)sh, N);
    sage_bf16<1><<<ggrid, THREADS_G, SMEM_TOTAL_BYTES>>>((const uint2*)h1h, (const uint2*)sh,
                                                         wfrag + 8192, bhl, h2h, N);

    // Layer 3
    gather_k<<<agrid, 256>>>((const uint2*)h2h, start, deg, esrc, (uint2*)sh, N);
    sage_out_k<<<ogrid, 256>>>((const uint2*)h2h, (const uint2*)sh,
                               W2l, b2l, W2r, out, N);
}

// round 17
// speedup vs baseline: 1.0986x; 1.0986x over previous
#include <cuda_runtime.h>
#include <cuda_fp16.h>
#include <math.h>

#define DHH 128
#define NMAX 50000
#define EMAX 800000
#define MT 64            // nodes per C tile
#define NTILES 16        // 16 n-tiles of 8 = 128 output feats
#define KST 16           // K-steps of 16 over fused K=256
#define THREADS_G 1024   // GEMM block: 32 warps
#define A_STRIDE 132                               // 128 k-pairs + 4 pad
#define SMEM_W_BYTES (KST * NTILES * 32 * 16)      // 8192 uint4 = 131072
#define SMEM_A_UINTS (MT * A_STRIDE)               // 8448
#define SMEM_TOTAL_BYTES (SMEM_W_BYTES + SMEM_A_UINTS * 4)   // ~165KB

// Scratch (allocation-free: static device globals).
// ALL node features (x/h1/h2 AND the aggregated mean s) stored fp16-packed:
// 64 uints (fp16x2) per node.
__device__ __align__(16) unsigned g_sh [NMAX * 64];
__device__ __align__(16) unsigned g_xh [NMAX * 64];
__device__ __align__(16) unsigned g_h1h[NMAX * 64];
__device__ __align__(16) unsigned g_h2h[NMAX * 64];
__device__ __align__(16) uint4 g_wfrag[2 * 8192];  // pre-split fp16 W fragments
__device__ int g_deg[NMAX];
__device__ int g_start[NMAX];
__device__ int g_cursor[NMAX];
__device__ int g_esrc[EMAX];
__device__ int g_alloc_ctr;

// ---------------------------------------------------------------------------
// fp16 helpers
// ---------------------------------------------------------------------------
__device__ __forceinline__ __half2 ash2(unsigned u) {
    return *reinterpret_cast<__half2*>(&u);
}
__device__ __forceinline__ unsigned packh2(float a, float b) {
    __half2 h = __floats2half2_rn(a, b);
    return *reinterpret_cast<unsigned*>(&h);
}
__device__ __forceinline__ float2 unpackh2(unsigned u) {
    return __half22float2(ash2(u));
}

// Split (x,y) into fp16x2 hi + fp16x2 lo residual (hi+lo ~ 22 mantissa bits).
__device__ __forceinline__ void split2h(float x, float y, unsigned& hi, unsigned& lo) {
    hi = packh2(x, y);
    float2 h = unpackh2(hi);
    lo = packh2(x - h.x, y - h.y);
}

// fp16 MMA, f32 accumulate
__device__ __forceinline__ void mma16h(float* c, const unsigned* a, unsigned b0, unsigned b1) {
    asm volatile("mma.sync.aligned.m16n8k16.row.col.f32.f16.f16.f32 "
        "{%0,%1,%2,%3}, {%4,%5,%6,%7}, {%8,%9}, {%0,%1,%2,%3};"
        : "+f"(c[0]), "+f"(c[1]), "+f"(c[2]), "+f"(c[3])
        : "r"(a[0]), "r"(a[1]), "r"(a[2]), "r"(a[3]), "r"(b0), "r"(b1));
}

// ---------------------------------------------------------------------------
// Convert x (f32) -> fp16
// ---------------------------------------------------------------------------
__global__ void convert_x(const float2* __restrict__ x, unsigned* __restrict__ xh, int n) {
    int i = blockIdx.x * blockDim.x + threadIdx.x;
    if (i < n) {
        float2 v = __ldg(&x[i]);
        xh[i] = packh2(v.x, v.y);
    }
}

// ---------------------------------------------------------------------------
// Prep: split W into fp16 hi/lo fragment order.
// Entry idx = layer*8192 + (S*16 + T)*32 + lane
//   S 0..15 over fused K (0..7 -> Wl, 8..15 -> Wr), T = n-tile
//   b0: W[T*8 + lane/4][k0 + 2cc, +1], b1: same at k0+8. uint4 = (h0,h1,l0,l1)
// ---------------------------------------------------------------------------
__global__ void prep_w(const float* __restrict__ W1l, const float* __restrict__ W1r,
                       const float* __restrict__ Whl, const float* __restrict__ Whr) {
    int idx = blockIdx.x * blockDim.x + threadIdx.x;
    if (idx >= 16384) return;
    int layer = idx >> 13;
    int rem = idx & 8191;
    int S = rem >> 9;
    int T = (rem >> 5) & 15;
    int lane = rem & 31;
    const float* W = (S < 8) ? (layer ? Whl : W1l) : (layer ? Whr : W1r);
    int k0 = (S & 7) * 16;
    int row = T * 8 + (lane >> 2);
    int cc = lane & 3;
    const float* p = W + row * DHH + k0 + 2 * cc;
    unsigned h0, l0, h1, l1;
    split2h(__ldg(&p[0]), __ldg(&p[1]), h0, l0);
    split2h(__ldg(&p[8]), __ldg(&p[9]), h1, l1);
    g_wfrag[idx] = make_uint4(h0, h1, l0, l1);
}

// ---------------------------------------------------------------------------
// CSR build: histogram -> warp-aggregated range allocation -> fill.
// ---------------------------------------------------------------------------
__global__ void hist_k(const int* __restrict__ ei, int E, int* __restrict__ deg) {
    int e = blockIdx.x * blockDim.x + threadIdx.x;
    if (e == 0) g_alloc_ctr = 0;   // nothing reads it until alloc_k
    if (e < E) atomicAdd(&deg[ei[E + e]], 1);
}

__global__ void alloc_k(const int* __restrict__ deg, int N,
                        int* __restrict__ start, int* __restrict__ cursor) {
    int i = blockIdx.x * blockDim.x + threadIdx.x;
    int lane = threadIdx.x & 31;
    int d = (i < N) ? deg[i] : 0;
    int pref = d;
    #pragma unroll
    for (int off = 1; off < 32; off <<= 1) {
        int v = __shfl_up_sync(0xffffffff, pref, off);
        if (lane >= off) pref += v;
    }
    int total = __shfl_sync(0xffffffff, pref, 31);
    int base = 0;
    if (lane == 31) base = atomicAdd(&g_alloc_ctr, total);
    base = __shfl_sync(0xffffffff, base, 31);
    int mybase = base + pref - d;
    if (i < N) {
        start[i] = mybase;
        cursor[i] = mybase;
    }
}

__global__ void fill_k(const int* __restrict__ ei, int E,
                       int* __restrict__ cursor, int* __restrict__ esrc) {
    int e = blockIdx.x * blockDim.x + threadIdx.x;
    if (e < E) {
        int dst = ei[E + e];
        int p = atomicAdd(&cursor[dst], 1);
        esrc[p] = ei[e];
    }
}

// ---------------------------------------------------------------------------
// Gather: one warp per dst node. fp16 feature reads, HADD2 partial sums over
// 4-edge groups, f32 master accumulator, fp16 packed output.
// Lane owns feats [4*lane .. 4*lane+3] = one uint2.
// ---------------------------------------------------------------------------
__global__ void gather_k(const uint2* __restrict__ feath, const int* __restrict__ start,
                         const int* __restrict__ deg, const int* __restrict__ esrc,
                         uint2* __restrict__ s, int N) {
    int n = blockIdx.x * 8 + (threadIdx.x >> 5);
    if (n >= N) return;
    int lane = threadIdx.x & 31;
    int beg = __ldg(&start[n]);
    int d = __ldg(&deg[n]);
    int end = beg + d;

    float4 acc = make_float4(0.f, 0.f, 0.f, 0.f);

    int e = beg;
    for (; e + 8 <= end; e += 8) {
        int s0 = __ldg(&esrc[e]),     s1 = __ldg(&esrc[e + 1]);
        int s2 = __ldg(&esrc[e + 2]), s3 = __ldg(&esrc[e + 3]);
        int s4 = __ldg(&esrc[e + 4]), s5 = __ldg(&esrc[e + 5]);
        int s6 = __ldg(&esrc[e + 6]), s7 = __ldg(&esrc[e + 7]);
        uint2 u0 = __ldg(&feath[(long long)s0 * 32 + lane]);
        uint2 u1 = __ldg(&feath[(long long)s1 * 32 + lane]);
        uint2 u2 = __ldg(&feath[(long long)s2 * 32 + lane]);
        uint2 u3 = __ldg(&feath[(long long)s3 * 32 + lane]);
        uint2 u4 = __ldg(&feath[(long long)s4 * 32 + lane]);
        uint2 u5 = __ldg(&feath[(long long)s5 * 32 + lane]);
        uint2 u6 = __ldg(&feath[(long long)s6 * 32 + lane]);
        uint2 u7 = __ldg(&feath[(long long)s7 * 32 + lane]);
        __half2 pa0 = __hadd2(ash2(u0.x), ash2(u1.x));
        __half2 pa1 = __hadd2(ash2(u0.y), ash2(u1.y));
        __half2 qa0 = __hadd2(ash2(u2.x), ash2(u3.x));
        __half2 qa1 = __hadd2(ash2(u2.y), ash2(u3.y));
        pa0 = __hadd2(pa0, qa0); pa1 = __hadd2(pa1, qa1);
        float2 fa0 = __half22float2(pa0), fa1 = __half22float2(pa1);
        acc.x += fa0.x; acc.y += fa0.y; acc.z += fa1.x; acc.w += fa1.y;
        __half2 pb0 = __hadd2(ash2(u4.x), ash2(u5.x));
        __half2 pb1 = __hadd2(ash2(u4.y), ash2(u5.y));
        __half2 qb0 = __hadd2(ash2(u6.x), ash2(u7.x));
        __half2 qb1 = __hadd2(ash2(u6.y), ash2(u7.y));
        pb0 = __hadd2(pb0, qb0); pb1 = __hadd2(pb1, qb1);
        float2 fb0 = __half22float2(pb0), fb1 = __half22float2(pb1);
        acc.x += fb0.x; acc.y += fb0.y; acc.z += fb1.x; acc.w += fb1.y;
    }
    for (; e + 4 <= end; e += 4) {
        int s0 = __ldg(&esrc[e]),     s1 = __ldg(&esrc[e + 1]);
        int s2 = __ldg(&esrc[e + 2]), s3 = __ldg(&esrc[e + 3]);
        uint2 u0 = __ldg(&feath[(long long)s0 * 32 + lane]);
        uint2 u1 = __ldg(&feath[(long long)s1 * 32 + lane]);
        uint2 u2 = __ldg(&feath[(long long)s2 * 32 + lane]);
        uint2 u3 = __ldg(&feath[(long long)s3 * 32 + lane]);
        __half2 p0 = __hadd2(ash2(u0.x), ash2(u1.x));
        __half2 p1 = __hadd2(ash2(u0.y), ash2(u1.y));
        __half2 q0 = __hadd2(ash2(u2.x), ash2(u3.x));
        __half2 q1 = __hadd2(ash2(u2.y), ash2(u3.y));
        p0 = __hadd2(p0, q0); p1 = __hadd2(p1, q1);
        float2 f0 = __half22float2(p0), f1 = __half22float2(p1);
        acc.x += f0.x; acc.y += f0.y; acc.z += f1.x; acc.w += f1.y;
    }
    for (; e < end; e++) {
        int s0 = __ldg(&esrc[e]);
        uint2 u0 = __ldg(&feath[(long long)s0 * 32 + lane]);
        float2 f0 = unpackh2(u0.x), f1 = unpackh2(u0.y);
        acc.x += f0.x; acc.y += f0.y; acc.z += f1.x; acc.w += f1.y;
    }

    float inv = 1.0f / fmaxf((float)d, 1.0f);
    uint2 r;
    r.x = packh2(acc.x * inv, acc.y * inv);
    r.y = packh2(acc.z * inv, acc.w * inv);
    s[(long long)n * 32 + lane] = r;
}

// ---------------------------------------------------------------------------
// Fused SAGE layer: C = act([agg | x] . [Wl|Wr]^T + bl), fp16 mma.
// A is exact fp16 (storage format), so only W is split (hi+lo): 2 MMAs/step.
// Block: 1024 threads / 32 warps. Warp w: rowgroup g = w>>3 (16 rows),
// ntile pair q = w&7 (tiles 2q, 2q+1). A staging = pure uint2 copies.
// ---------------------------------------------------------------------------
template <int ACT>
__global__ __launch_bounds__(THREADS_G, 1)
void sage_f16(const uint2* __restrict__ xh, const uint2* __restrict__ sh,
              const uint4* __restrict__ wfrag, const float* __restrict__ bl,
              unsigned* __restrict__ outh, int N) {
    extern __shared__ char smemraw[];
    uint4*    shW = (uint4*)smemraw;                        // [KST*NTILES*32] = 8192
    unsigned* shA = (unsigned*)(smemraw + SMEM_W_BYTES);    // [MT][A_STRIDE]

    int t = threadIdx.x;
    int w = t >> 5, lane = t & 31;
    int r = lane >> 2, c = lane & 3;
    int g = w >> 3;        // row-group 0..3
    int q = w & 7;         // ntile pair 0..7
    int mbase = g * 16;

    // 8192 uint4 entries staged by 1024 threads: 8 iterations.
    #pragma unroll
    for (int i = 0; i < 8; i++)
        shW[t + i * THREADS_G] = __ldg(&wfrag[t + i * THREADS_G]);

    float bias0[2], bias1[2];
    #pragma unroll
    for (int i = 0; i < 2; i++) {
        int colg = (q * 2 + i) * 8 + 2 * c;
        bias0[i] = __ldg(&bl[colg]);
        bias1[i] = __ldg(&bl[colg + 1]);
    }

    int mtiles = (N + MT - 1) / MT;
    for (int tile = blockIdx.x; tile < mtiles; tile += gridDim.x) {
        __syncthreads();
        int n0 = tile * MT;

        // A tile: 64 rows x 64 uint2 (fused [s | x], raw fp16 copies)
        #pragma unroll
        for (int i = 0; i < 4; i++) {
            int flat = t + i * THREADS_G;      // 0..4095
            int row = flat >> 6;
            int c4 = flat & 63;
            int node = n0 + row;
            uint2 u = make_uint2(0u, 0u);
            if (node < N) {
                u = (c4 < 32)
                    ? __ldg(&sh[(long long)node * 32 + c4])
                    : __ldg(&xh[(long long)node * 32 + (c4 - 32)]);
            }
            *(uint2*)&shA[row * A_STRIDE + c4 * 2] = u;
        }
        __syncthreads();

        float acc[2][4];
        #pragma unroll
        for (int T = 0; T < 2; T++)
            acc[T][0] = acc[T][1] = acc[T][2] = acc[T][3] = 0.f;

        #pragma unroll 4
        for (int S = 0; S < KST; S++) {
            int ra = (mbase + r) * A_STRIDE + S * 8 + c;
            int rb = (mbase + r + 8) * A_STRIDE + S * 8 + c;
            unsigned a[4];
            a[0] = shA[ra]; a[1] = shA[rb]; a[2] = shA[ra + 4]; a[3] = shA[rb + 4];
            #pragma unroll
            for (int T = 0; T < 2; T++) {
                uint4 b = shW[(S * NTILES + q * 2 + T) * 32 + lane];
                mma16h(acc[T], a, b.z, b.w);   // a * Wlo
                mma16h(acc[T], a, b.x, b.y);   // a * Whi
            }
        }

        #pragma unroll
        for (int T = 0; T < 2; T++) {
            int colg = (q * 2 + T) * 8 + 2 * c;
            float v0 = acc[T][0] + bias0[T], v1 = acc[T][1] + bias1[T];
            float v2 = acc[T][2] + bias0[T], v3 = acc[T][3] + bias1[T];
            if (ACT == 0) {
                v0 = fmaxf(v0, 0.f); v1 = fmaxf(v1, 0.f);
                v2 = fmaxf(v2, 0.f); v3 = fmaxf(v3, 0.f);
            } else {
                v0 = (v0 > 0.f) ? v0 : expm1f(v0);
                v1 = (v1 > 0.f) ? v1 : expm1f(v1);
                v2 = (v2 > 0.f) ? v2 : expm1f(v2);
                v3 = (v3 > 0.f) ? v3 : expm1f(v3);
            }
            int node0 = n0 + mbase + r;
            int cw = colg >> 1;                 // uint word index within row
            if (node0 < N)
                outh[(long long)node0 * 64 + cw] = packh2(v0, v1);
            if (node0 + 8 < N)
                outh[(long long)(node0 + 8) * 64 + cw] = packh2(v2, v3);
        }
    }
}

// ---------------------------------------------------------------------------
// Output layer (DOUT=8) + log_softmax. One warp per node.
// Lane owns feats [4*lane..4*lane+3]; weights via vector LDG.128 (coalesced).
// ---------------------------------------------------------------------------
__global__ void sage_out_k(const uint2* __restrict__ xh, const uint2* __restrict__ sh,
                           const float* __restrict__ Wl, const float* __restrict__ bl,
                           const float* __restrict__ Wr,
                           float* __restrict__ out, int N) {
    long long tid = (long long)blockIdx.x * blockDim.x + threadIdx.x;
    int n = (int)(tid >> 5);
    if (n >= N) return;
    int lane = (int)(tid & 31);

    uint2 su = __ldg(&sh[(long long)n * 32 + lane]);
    uint2 xu = __ldg(&xh[(long long)n * 32 + lane]);
    float2 s01 = unpackh2(su.x), s23 = unpackh2(su.y);
    float2 x01 = unpackh2(xu.x), x23 = unpackh2(xu.y);

    float acc[8];
    #pragma unroll
    for (int j = 0; j < 8; j++) {
        float4 wl = __ldg((const float4*)(Wl + j * DHH) + lane);
        float4 wr = __ldg((const float4*)(Wr + j * DHH) + lane);
        acc[j] = s01.x * wl.x + s01.y * wl.y + s23.x * wl.z + s23.y * wl.w
               + x01.x * wr.x + x01.y * wr.y + x23.x * wr.z + x23.y * wr.w;
    }

    #pragma unroll
    for (int j = 0; j < 8; j++) {
        #pragma unroll
        for (int off = 16; off > 0; off >>= 1)
            acc[j] += __shfl_xor_sync(0xffffffff, acc[j], off);
    }

    if (lane == 0) {
        float h[8];
        float m = -1e30f;
        #pragma unroll
        for (int j = 0; j < 8; j++) {
            h[j] = acc[j] + bl[j];
            m = fmaxf(m, h[j]);
        }
        float sum = 0.0f;
        #pragma unroll
        for (int j = 0; j < 8; j++) sum += expf(h[j] - m);
        float lse = logf(sum) + m;
        #pragma unroll
        for (int j = 0; j < 8; j++) out[(long long)n * 8 + j] = h[j] - lse;
    }
}

// ---------------------------------------------------------------------------
extern "C" void kernel_launch(void* const* d_in, const int* in_sizes, int n_in,
                              void* d_out, int out_size) {
    const float* x   = (const float*)d_in[0];
    const int*   ei  = (const int*)d_in[1];
    // d_in[2] = edge_attr, unused
    const float* W1l = (const float*)d_in[3];
    const float* b1l = (const float*)d_in[4];
    const float* W1r = (const float*)d_in[5];
    const float* Whl = (const float*)d_in[6];
    const float* bhl = (const float*)d_in[7];
    const float* Whr = (const float*)d_in[8];
    const float* W2l = (const float*)d_in[9];
    const float* b2l = (const float*)d_in[10];
    const float* W2r = (const float*)d_in[11];
    float* out = (float*)d_out;

    int N = in_sizes[0] / DHH;
    int E = in_sizes[1] / 2;

    unsigned *sh, *xh, *h1h, *h2h;
    uint4* wfrag;
    int *deg, *start, *cursor, *esrc;
    cudaGetSymbolAddress((void**)&sh, g_sh);
    cudaGetSymbolAddress((void**)&xh, g_xh);
    cudaGetSymbolAddress((void**)&h1h, g_h1h);
    cudaGetSymbolAddress((void**)&h2h, g_h2h);
    cudaGetSymbolAddress((void**)&wfrag, g_wfrag);
    cudaGetSymbolAddress((void**)&deg, g_deg);
    cudaGetSymbolAddress((void**)&start, g_start);
    cudaGetSymbolAddress((void**)&cursor, g_cursor);
    cudaGetSymbolAddress((void**)&esrc, g_esrc);

    cudaFuncSetAttribute(sage_f16<0>, cudaFuncAttributeMaxDynamicSharedMemorySize,
                         SMEM_TOTAL_BYTES);
    cudaFuncSetAttribute(sage_f16<1>, cudaFuncAttributeMaxDynamicSharedMemorySize,
                         SMEM_TOTAL_BYTES);

    int egrid = (E + 255) / 256;
    int ngrid = (N + 255) / 256;
    int cgrid = (N * 64 + 255) / 256;
    int ggrid = 148;
    int agrid = (N + 7) / 8;
    int ogrid = (int)(((long long)N * 32 + 255) / 256);

    // CSR build + fp16 conversion of x
    cudaMemsetAsync(deg, 0, (size_t)N * sizeof(int), 0);
    convert_x<<<cgrid, 256>>>((const float2*)x, xh, N * 64);
    hist_k<<<egrid, 256>>>(ei, E, deg);
    alloc_k<<<ngrid, 256>>>(deg, N, start, cursor);
    fill_k<<<egrid, 256>>>(ei, E, cursor, esrc);

    // Layer 1 (prep_w needs to finish only before sage_f16<0>)
    gather_k<<<agrid, 256>>>((const uint2*)xh, start, deg, esrc, (uint2*)sh, N);
    prep_w<<<64, 256>>>(W1l, W1r, Whl, Whr);
    sage_f16<0><<<ggrid, THREADS_G, SMEM_TOTAL_BYTES>>>((const uint2*)xh, (const uint2*)sh,
                                                        wfrag, b1l, h1h, N);

    // Layer 2
    gather_k<<<agrid, 256>>>((const uint2*)h1h, start, deg, esrc, (uint2*)sh, N);
    sage_f16<1><<<ggrid, THREADS_G, SMEM_TOTAL_BYTES>>>((const uint2*)h1h, (const uint2*)sh,
                                                        wfrag + 8192, bhl, h2h, N);

    // Layer 3
    gather_k<<<agrid, 256>>>((const uint2*)h2h, start, deg, esrc, (uint2*)sh, N);
    sage_out_k<<<ogrid, 256>>>((const uint2*)h2h, (const uint2*)sh,
                               W2l, b2l, W2r, out, N);
}